// round 4
// baseline (speedup 1.0000x reference)
#include <cuda_runtime.h>
#include <math.h>

// RMAC: x [64, 2048, 16, 16] f32 -> out [64, 14*2048] f32, L2-normalized per batch.
// Regions: L1 1x(16x16), L2 4x(10x10, starts {0,4}), L3 9x(8x8, starts {0,3,6}).

#define B_TOT   64
#define C_TOT   2048
#define NREG    14
#define OUT_PER_B (NREG * C_TOT)   // 28672

#define CHB     32                  // channels per block
#define TPB     128                 // threads per block (4 threads per channel)
#define SSTRIDE 257                 // padded smem row stride (words), odd -> conflict-free

__device__ float g_sumsq[B_TOT];

__global__ void rmac_zero_kernel() {
    if (threadIdx.x < B_TOT) g_sumsq[threadIdx.x] = 0.0f;
}

__global__ __launch_bounds__(TPB) void rmac_main_kernel(
    const float* __restrict__ x, float* __restrict__ out)
{
    __shared__ float sm[CHB * SSTRIDE];   // 32*257*4 = 32896 B

    const int b  = blockIdx.y;
    const int c0 = blockIdx.x * CHB;
    const int t  = threadIdx.x;

    // ---- Phase 1: stage 32 contiguous channels (32 KiB) coalesced into smem ----
    const float* __restrict__ g = x + ((size_t)b * C_TOT + c0) * 256;
    #pragma unroll
    for (int i = 0; i < 64; i++) {
        int w  = i * TPB + t;        // 0..8191, consecutive across lanes
        int ch = w >> 8;             // channel within block
        int wl = w & 255;            // word within channel
        sm[ch * SSTRIDE + wl] = g[w];
    }
    __syncthreads();

    // ---- Phase 2: each thread pools 4 rows of one channel ----
    const int ch     = t & (CHB - 1);    // lanes of a warp hit 32 distinct channels
    const int rchunk = t >> 5;           // 0..3 -> rows 4*rchunk .. 4*rchunk+3
    const float* __restrict__ chp = sm + ch * SSTRIDE;

    float acc[NREG];
    #pragma unroll
    for (int r = 0; r < NREG; r++) acc[r] = 0.0f;

    #pragma unroll
    for (int rr = 0; rr < 4; rr++) {
        const int h = rchunk * 4 + rr;
        const float* __restrict__ rp = chp + h * 16;

        // 16-wide prefix sum in registers
        float pre[17];
        pre[0] = 0.0f;
        float p = 0.0f;
        #pragma unroll
        for (int j = 0; j < 16; j++) { p += rp[j]; pre[j + 1] = p; }

        const float s16  = pre[16];              // cols [0,16)
        const float c10a = pre[10];              // cols [0,10)
        const float c10b = pre[14] - pre[4];     // cols [4,14)
        const float c8a  = pre[8];               // cols [0,8)
        const float c8b  = pre[11] - pre[3];     // cols [3,11)
        const float c8c  = pre[14] - pre[6];     // cols [6,14)

        acc[0] += s16;                                           // L1 rows [0,16)
        if (h < 10)           { acc[1]  += c10a; acc[2]  += c10b; }   // L2 rows [0,10)
        if (h >= 4 && h < 14) { acc[3]  += c10a; acc[4]  += c10b; }   // L2 rows [4,14)
        if (h < 8)            { acc[5]  += c8a;  acc[6]  += c8b;  acc[7]  += c8c; } // L3 r[0,8)
        if (h >= 3 && h < 11) { acc[8]  += c8a;  acc[9]  += c8b;  acc[10] += c8c; } // L3 r[3,11)
        if (h >= 6 && h < 14) { acc[11] += c8a;  acc[12] += c8b;  acc[13] += c8c; } // L3 r[6,14)
    }
    __syncthreads();

    // ---- Phase 3: combine the 4 row-chunk partials per channel via smem ----
    float* red = sm;                     // reuse: needs 14*128 = 1792 floats
    #pragma unroll
    for (int r = 0; r < NREG; r++) red[r * TPB + t] = acc[r];
    __syncthreads();

    float ss = 0.0f;
    float* __restrict__ outb = out + (size_t)b * OUT_PER_B;
    #pragma unroll
    for (int idx = t; idx < NREG * CHB; idx += TPB) {   // 448 outputs
        const int r  = idx >> 5;          // region 0..13
        const int cc = idx & 31;          // channel within block
        float v = red[r * TPB + cc]      + red[r * TPB + cc + 32]
                + red[r * TPB + cc + 64] + red[r * TPB + cc + 96];
        const float inv_area = (r == 0) ? (1.0f / 256.0f)
                              : (r < 5) ? (1.0f / 100.0f)
                                        : (1.0f / 64.0f);
        v *= inv_area;
        outb[r * C_TOT + c0 + cc] = v;    // coalesced within 64-wide segments
        ss += v * v;
    }

    // warp-reduce the sum of squares, one atomic per warp
    #pragma unroll
    for (int o = 16; o > 0; o >>= 1)
        ss += __shfl_down_sync(0xffffffffu, ss, o);
    if ((t & 31) == 0) atomicAdd(&g_sumsq[b], ss);
}

__global__ __launch_bounds__(256) void rmac_norm_kernel(float* __restrict__ out) {
    const int b = blockIdx.y;
    const int i = (blockIdx.x * 256 + threadIdx.x);   // float4 index, < 7168
    const float n   = fmaxf(sqrtf(g_sumsq[b]), 1e-12f);
    const float inv = 1.0f / n;
    float4* p = reinterpret_cast<float4*>(out + (size_t)b * OUT_PER_B) + i;
    float4 v = *p;
    v.x *= inv; v.y *= inv; v.z *= inv; v.w *= inv;
    *p = v;
}

extern "C" void kernel_launch(void* const* d_in, const int* in_sizes, int n_in,
                              void* d_out, int out_size) {
    (void)in_sizes; (void)n_in; (void)out_size;
    const float* x = (const float*)d_in[0];
    float* out = (float*)d_out;

    rmac_zero_kernel<<<1, 64>>>();

    dim3 g1(C_TOT / CHB, B_TOT);                 // (64, 64) blocks
    rmac_main_kernel<<<g1, TPB>>>(x, out);

    dim3 g2(OUT_PER_B / (256 * 4), B_TOT);       // (28, 64) blocks, float4
    rmac_norm_kernel<<<g2, 256>>>(out);
}

// round 5
// speedup vs baseline: 1.0553x; 1.0553x over previous
#include <cuda_runtime.h>
#include <math.h>

// RMAC: x [64, 2048, 16, 16] f32 -> out [64, 14*2048] f32, L2-normalized per batch.
// Regions: L1 1x(16x16), L2 4x(10x10, starts {0,4}), L3 9x(8x8, starts {0,3,6}).

#define B_TOT   64
#define C_TOT   2048
#define NREG    14
#define OUT_PER_B (NREG * C_TOT)   // 28672

#define CHB     32                  // channels per block
#define TPB     128                 // threads per block (4 threads per channel)

__global__ __launch_bounds__(TPB) void rmac_main_kernel(
    const float* __restrict__ x, float* __restrict__ out)
{
    // 32 channels x 256 words, no pad; XOR-swizzled at float4 granularity.
    __shared__ float sm[CHB * 256];   // 32768 B exactly -> 6 blocks/SM

    const int b  = blockIdx.y;
    const int c0 = blockIdx.x * CHB;
    const int t  = threadIdx.x;

    // ---- Phase 1: stage 32 contiguous channels (32 KiB) via LDG.128 ----
    const float4* __restrict__ gv =
        reinterpret_cast<const float4*>(x + ((size_t)b * C_TOT + c0) * 256);
    float4* smv = reinterpret_cast<float4*>(sm);
    #pragma unroll
    for (int i = 0; i < 16; i++) {
        const int q  = i * TPB + t;     // float4 index 0..2047, consecutive across lanes
        const int ch = q >> 6;          // 64 float4 per channel
        const int qw = q & 63;
        smv[ch * 64 + (qw ^ (ch & 7))] = gv[q];   // STS.128, conflict-free
    }
    __syncthreads();

    // ---- Phase 2: each thread pools 4 rows of one channel ----
    const int ch     = t & (CHB - 1);    // lanes of a warp -> 32 distinct channels
    const int rchunk = t >> 5;           // rows 4*rchunk .. 4*rchunk+3
    const float4* __restrict__ cv = smv + ch * 64;
    const int sw = ch & 7;

    float acc[NREG];
    #pragma unroll
    for (int r = 0; r < NREG; r++) acc[r] = 0.0f;

    #pragma unroll
    for (int rr = 0; rr < 4; rr++) {
        const int h = rchunk * 4 + rr;

        // read the 16-element row as 4 swizzled float4s (LDS.128, conflict-free)
        float rowv[16];
        #pragma unroll
        for (int jj = 0; jj < 4; jj++) {
            const float4 v = cv[(h * 4 + jj) ^ sw];
            rowv[jj * 4 + 0] = v.x; rowv[jj * 4 + 1] = v.y;
            rowv[jj * 4 + 2] = v.z; rowv[jj * 4 + 3] = v.w;
        }

        // 16-wide prefix sum in registers
        float pre[17];
        pre[0] = 0.0f;
        float p = 0.0f;
        #pragma unroll
        for (int j = 0; j < 16; j++) { p += rowv[j]; pre[j + 1] = p; }

        const float s16  = pre[16];              // cols [0,16)
        const float c10a = pre[10];              // cols [0,10)
        const float c10b = pre[14] - pre[4];     // cols [4,14)
        const float c8a  = pre[8];               // cols [0,8)
        const float c8b  = pre[11] - pre[3];     // cols [3,11)
        const float c8c  = pre[14] - pre[6];     // cols [6,14)

        acc[0] += s16;                                                // L1 rows [0,16)
        if (h < 10)           { acc[1]  += c10a; acc[2]  += c10b; }   // L2 rows [0,10)
        if (h >= 4 && h < 14) { acc[3]  += c10a; acc[4]  += c10b; }   // L2 rows [4,14)
        if (h < 8)            { acc[5]  += c8a;  acc[6]  += c8b;  acc[7]  += c8c; } // L3 r[0,8)
        if (h >= 3 && h < 11) { acc[8]  += c8a;  acc[9]  += c8b;  acc[10] += c8c; } // L3 r[3,11)
        if (h >= 6 && h < 14) { acc[11] += c8a;  acc[12] += c8b;  acc[13] += c8c; } // L3 r[6,14)
    }
    __syncthreads();

    // ---- Phase 3: combine the 4 row-chunk partials per channel via smem ----
    float* red = sm;                     // reuse: 14*128 = 1792 floats
    #pragma unroll
    for (int r = 0; r < NREG; r++) red[r * TPB + t] = acc[r];
    __syncthreads();

    float* __restrict__ outb = out + (size_t)b * OUT_PER_B;
    #pragma unroll
    for (int idx = t; idx < NREG * CHB; idx += TPB) {   // 448 outputs
        const int r  = idx >> 5;          // region 0..13
        const int cc = idx & 31;          // channel within block
        float v = red[r * TPB + cc]      + red[r * TPB + cc + 32]
                + red[r * TPB + cc + 64] + red[r * TPB + cc + 96];
        const float inv_area = (r == 0) ? (1.0f / 256.0f)
                              : (r < 5) ? (1.0f / 100.0f)
                                        : (1.0f / 64.0f);
        outb[r * C_TOT + c0 + cc] = v * inv_area;   // coalesced in 128B segments
    }
}

// One block per batch row: self-contained sumsq + scale. Values stay in
// registers between the reduce and the write (single read pass).
__global__ __launch_bounds__(1024) void rmac_norm_kernel(float* __restrict__ out) {
    const int b = blockIdx.x;
    const int t = threadIdx.x;
    float4* __restrict__ p = reinterpret_cast<float4*>(out + (size_t)b * OUT_PER_B);

    float4 v[7];                       // 7168 float4 / 1024 threads = 7 each
    float ss = 0.0f;
    #pragma unroll
    for (int i = 0; i < 7; i++) {
        v[i] = p[i * 1024 + t];
        ss += v[i].x * v[i].x + v[i].y * v[i].y
            + v[i].z * v[i].z + v[i].w * v[i].w;
    }

    // block reduction
    #pragma unroll
    for (int o = 16; o > 0; o >>= 1)
        ss += __shfl_down_sync(0xffffffffu, ss, o);

    __shared__ float wsum[32];
    const int lane = t & 31, wid = t >> 5;
    if (lane == 0) wsum[wid] = ss;
    __syncthreads();
    if (wid == 0) {
        float s = wsum[lane];
        #pragma unroll
        for (int o = 16; o > 0; o >>= 1)
            s += __shfl_down_sync(0xffffffffu, s, o);
        if (lane == 0) wsum[0] = s;
    }
    __syncthreads();

    const float inv = 1.0f / fmaxf(sqrtf(wsum[0]), 1e-12f);
    #pragma unroll
    for (int i = 0; i < 7; i++) {
        v[i].x *= inv; v[i].y *= inv; v[i].z *= inv; v[i].w *= inv;
        p[i * 1024 + t] = v[i];
    }
}

extern "C" void kernel_launch(void* const* d_in, const int* in_sizes, int n_in,
                              void* d_out, int out_size) {
    (void)in_sizes; (void)n_in; (void)out_size;
    const float* x = (const float*)d_in[0];
    float* out = (float*)d_out;

    dim3 g1(C_TOT / CHB, B_TOT);                 // (64, 64) blocks
    rmac_main_kernel<<<g1, TPB>>>(x, out);

    rmac_norm_kernel<<<B_TOT, 1024>>>(out);      // 64 blocks
}

// round 13
// speedup vs baseline: 1.1963x; 1.1336x over previous
#include <cuda_runtime.h>
#include <cstdint>
#include <math.h>

// RMAC: x [64, 2048, 16, 16] f32 -> out [64, 14*2048] f32, L2-normalized per batch.
// Regions: L1 1x(16x16), L2 4x(10x10, starts {0,4}), L3 9x(8x8, starts {0,3,6}).

#define B_TOT   64
#define C_TOT   2048
#define NREG    14
#define OUT_PER_B (NREG * C_TOT)        // 28672

#define CHB     16                      // channels per tile
#define TPB     128                     // threads per block
#define TILE_F4 (CHB * 64)              // 1024 float4 per tile (16 KiB)
#define TILE_W  (CHB * 256)             // 4096 floats
#define NTILES  (B_TOT * (C_TOT / CHB)) // 8192
#define GRID_MAIN 888                   // persistent: 148 SMs x 6 blocks
#define RSTRIDE 144                     // phase-3 smem stride (conflict-free combine)

__device__ float g_part[NTILES];        // per-tile sum of squares (overwritten each run)

__device__ __forceinline__ void cp16(unsigned int s, const void* g) {
    asm volatile("cp.async.cg.shared.global [%0], [%1], 16;" :: "r"(s), "l"(g) : "memory");
}
__device__ __forceinline__ void cp_commit() {
    asm volatile("cp.async.commit_group;" ::: "memory");
}
__device__ __forceinline__ void cp_wait1() {
    asm volatile("cp.async.wait_group 1;" ::: "memory");
}

__global__ __launch_bounds__(TPB) void rmac_main_kernel(
    const float* __restrict__ x, float* __restrict__ out)
{
    __shared__ __align__(16) float sm[2 * TILE_W];   // 32 KiB, double buffer
    const int t = threadIdx.x;
    const unsigned int sbase = (unsigned int)__cvta_generic_to_shared(sm);

    // issue the 16 KiB tile load into buffer p (swizzled STS via cp.async)
    auto issue = [&](int tile, int p) {
        const float4* __restrict__ gv =
            reinterpret_cast<const float4*>(x) + (size_t)tile * TILE_F4;  // tiles contiguous
        const unsigned int bb = sbase + (unsigned int)p * (TILE_W * 4);
        #pragma unroll
        for (int i = 0; i < TILE_F4 / TPB; i++) {    // 8 x cp.async per thread
            const int q  = i * TPB + t;              // consecutive across lanes
            const int ch = q >> 6;
            const int qw = q & 63;
            cp16(bb + (unsigned int)((ch * 64 + (qw ^ (ch & 7))) * 16), gv + q);
        }
    };

    const int t0 = blockIdx.x;
    if (t0 < NTILES) issue(t0, 0);
    cp_commit();
    if (t0 + GRID_MAIN < NTILES) issue(t0 + GRID_MAIN, 1);
    cp_commit();

    const int ch     = t & (CHB - 1);   // channel within tile
    const int rchunk = t >> 4;          // 0..7 -> rows 2*rchunk, 2*rchunk+1
    const int sw     = ch & 7;

    int j = 0;
    for (int tile = t0; tile < NTILES; tile += GRID_MAIN, j++) {
        float* cur = sm + (j & 1) * TILE_W;
        const float4* __restrict__ cv = reinterpret_cast<const float4*>(cur) + ch * 64;

        cp_wait1();          // tile j landed (tile j+1 may still be in flight)
        __syncthreads();

        // ---- pool 2 rows of one channel ----
        float acc[NREG];
        #pragma unroll
        for (int r = 0; r < NREG; r++) acc[r] = 0.0f;

        #pragma unroll
        for (int rr = 0; rr < 2; rr++) {
            const int h = rchunk * 2 + rr;
            float rowv[16];
            #pragma unroll
            for (int jj = 0; jj < 4; jj++) {
                const float4 v = cv[(h * 4 + jj) ^ sw];   // LDS.128, conflict-free
                rowv[jj*4+0] = v.x; rowv[jj*4+1] = v.y;
                rowv[jj*4+2] = v.z; rowv[jj*4+3] = v.w;
            }
            float pre[17];
            pre[0] = 0.0f;
            float p = 0.0f;
            #pragma unroll
            for (int q = 0; q < 16; q++) { p += rowv[q]; pre[q + 1] = p; }

            const float s16  = pre[16];
            const float c10a = pre[10];
            const float c10b = pre[14] - pre[4];
            const float c8a  = pre[8];
            const float c8b  = pre[11] - pre[3];
            const float c8c  = pre[14] - pre[6];

            acc[0] += s16;
            if (h < 10)           { acc[1]  += c10a; acc[2]  += c10b; }
            if (h >= 4 && h < 14) { acc[3]  += c10a; acc[4]  += c10b; }
            if (h < 8)            { acc[5]  += c8a;  acc[6]  += c8b;  acc[7]  += c8c; }
            if (h >= 3 && h < 11) { acc[8]  += c8a;  acc[9]  += c8b;  acc[10] += c8c; }
            if (h >= 6 && h < 14) { acc[11] += c8a;  acc[12] += c8b;  acc[13] += c8c; }
        }
        __syncthreads();     // everyone done reading cur before reusing it

        // ---- combine 8 row-chunk partials per channel via smem (reuse cur) ----
        float* red = cur;                       // 14 * 144 = 2016 floats
        #pragma unroll
        for (int r = 0; r < NREG; r++) red[r * RSTRIDE + t] = acc[r];
        __syncthreads();

        const int b  = tile >> 7;               // 128 tiles per batch
        const int c0 = (tile & 127) * CHB;
        float* __restrict__ outb = out + (size_t)b * OUT_PER_B;
        float ss = 0.0f;
        #pragma unroll
        for (int idx = t; idx < NREG * CHB; idx += TPB) {   // 224 outputs
            const int r  = idx >> 4;
            const int cc = idx & 15;
            float v = 0.0f;
            #pragma unroll
            for (int k = 0; k < 8; k++) v += red[r * RSTRIDE + cc + 16 * k];
            const float inv_area = (r == 0) ? (1.0f / 256.0f)
                                  : (r < 5) ? (1.0f / 100.0f)
                                            : (1.0f / 64.0f);
            v *= inv_area;
            outb[r * C_TOT + c0 + cc] = v;
            ss += v * v;
        }

        // block-reduce ss -> g_part[tile] (plain store, no atomics)
        #pragma unroll
        for (int o = 16; o > 0; o >>= 1)
            ss += __shfl_down_sync(0xffffffffu, ss, o);
        float* wsum = cur + 2048;               // beyond red area, inside buffer
        if ((t & 31) == 0) wsum[t >> 5] = ss;
        __syncthreads();
        if (t == 0) g_part[tile] = wsum[0] + wsum[1] + wsum[2] + wsum[3];
        __syncthreads();     // cur fully consumed -> safe to refill

        const int nt = tile + 2 * GRID_MAIN;
        if (nt < NTILES) issue(nt, j & 1);
        cp_commit();         // commit every iteration to keep group accounting simple
    }
}

// 448 blocks: each reduces its batch's 128 partials (L2-hit) and scales one slice.
__global__ __launch_bounds__(256) void rmac_norm_kernel(float* __restrict__ out) {
    const int b = blockIdx.y;
    const int s = blockIdx.x;       // 0..6
    const int t = threadIdx.x;
    __shared__ float sinv;

    if (t < 32) {
        float v = g_part[b * 128 + t]      + g_part[b * 128 + t + 32]
                + g_part[b * 128 + t + 64] + g_part[b * 128 + t + 96];
        #pragma unroll
        for (int o = 16; o > 0; o >>= 1)
            v += __shfl_down_sync(0xffffffffu, v, o);
        if (t == 0) sinv = 1.0f / fmaxf(sqrtf(v), 1e-12f);
    }
    __syncthreads();
    const float inv = sinv;

    float4* __restrict__ p =
        reinterpret_cast<float4*>(out + (size_t)b * OUT_PER_B) + s * 1024 + t;
    #pragma unroll
    for (int k = 0; k < 4; k++) {
        float4 v = p[k * 256];
        v.x *= inv; v.y *= inv; v.z *= inv; v.w *= inv;
        p[k * 256] = v;
    }
}

extern "C" void kernel_launch(void* const* d_in, const int* in_sizes, int n_in,
                              void* d_out, int out_size) {
    (void)in_sizes; (void)n_in; (void)out_size;
    const float* x = (const float*)d_in[0];
    float* out = (float*)d_out;

    rmac_main_kernel<<<GRID_MAIN, TPB>>>(x, out);

    dim3 gn(OUT_PER_B / (256 * 4 * 4), B_TOT);   // (7, 64) = 448 blocks
    rmac_norm_kernel<<<gn, 256>>>(out);
}

// round 14
// speedup vs baseline: 1.2100x; 1.0114x over previous
#include <cuda_runtime.h>
#include <cstdint>
#include <math.h>

// RMAC: x [64, 2048, 16, 16] f32 -> out [64, 14*2048] f32, L2-normalized per batch.
// Regions: L1 1x(16x16), L2 4x(10x10, starts {0,4}), L3 9x(8x8, starts {0,3,6}).

#define B_TOT   64
#define C_TOT   2048
#define NREG    14
#define OUT_PER_B (NREG * C_TOT)        // 28672

#define CHB     16                      // channels per tile
#define TPB     128                     // threads per block
#define TILE_F4 (CHB * 64)              // 1024 float4 per tile (16 KiB)
#define TILE_W  (CHB * 256)             // 4096 floats
#define NTILES  (B_TOT * (C_TOT / CHB)) // 8192
#define GRID_MAIN 888                   // persistent: 148 SMs x 6 blocks
#define RSTRIDE 144                     // phase-3 smem stride (conflict-free combine)

__device__ float g_part[NTILES];        // per-tile sum of squares (overwritten each run)

__device__ __forceinline__ void cp16(unsigned int s, const void* g) {
    asm volatile("cp.async.cg.shared.global [%0], [%1], 16;" :: "r"(s), "l"(g) : "memory");
}
__device__ __forceinline__ void cp_commit() {
    asm volatile("cp.async.commit_group;" ::: "memory");
}
__device__ __forceinline__ void cp_wait1() {
    asm volatile("cp.async.wait_group 1;" ::: "memory");
}

__global__ __launch_bounds__(TPB) void rmac_main_kernel(
    const float* __restrict__ x, float* __restrict__ out)
{
    __shared__ __align__(16) float sm[2 * TILE_W];   // 32 KiB, double buffer
    const int t = threadIdx.x;
    const unsigned int sbase = (unsigned int)__cvta_generic_to_shared(sm);

    // issue the 16 KiB tile load into buffer p (swizzled STS via cp.async)
    auto issue = [&](int tile, int p) {
        const float4* __restrict__ gv =
            reinterpret_cast<const float4*>(x) + (size_t)tile * TILE_F4;  // tiles contiguous
        const unsigned int bb = sbase + (unsigned int)p * (TILE_W * 4);
        #pragma unroll
        for (int i = 0; i < TILE_F4 / TPB; i++) {    // 8 x cp.async per thread
            const int q  = i * TPB + t;              // consecutive across lanes
            const int ch = q >> 6;
            const int qw = q & 63;
            cp16(bb + (unsigned int)((ch * 64 + (qw ^ (ch & 7))) * 16), gv + q);
        }
    };

    const int t0 = blockIdx.x;
    if (t0 < NTILES) issue(t0, 0);
    cp_commit();
    if (t0 + GRID_MAIN < NTILES) issue(t0 + GRID_MAIN, 1);
    cp_commit();

    const int ch     = t & (CHB - 1);   // channel within tile
    const int rchunk = t >> 4;          // 0..7 -> rows 2*rchunk, 2*rchunk+1
    const int sw     = ch & 7;

    int j = 0;
    for (int tile = t0; tile < NTILES; tile += GRID_MAIN, j++) {
        float* cur = sm + (j & 1) * TILE_W;
        const float4* __restrict__ cv = reinterpret_cast<const float4*>(cur) + ch * 64;

        cp_wait1();          // tile j landed (tile j+1 may still be in flight)
        __syncthreads();

        // ---- pool 2 rows of one channel ----
        float acc[NREG];
        #pragma unroll
        for (int r = 0; r < NREG; r++) acc[r] = 0.0f;

        #pragma unroll
        for (int rr = 0; rr < 2; rr++) {
            const int h = rchunk * 2 + rr;
            float rowv[16];
            #pragma unroll
            for (int jj = 0; jj < 4; jj++) {
                const float4 v = cv[(h * 4 + jj) ^ sw];   // LDS.128, conflict-free
                rowv[jj*4+0] = v.x; rowv[jj*4+1] = v.y;
                rowv[jj*4+2] = v.z; rowv[jj*4+3] = v.w;
            }
            float pre[17];
            pre[0] = 0.0f;
            float p = 0.0f;
            #pragma unroll
            for (int q = 0; q < 16; q++) { p += rowv[q]; pre[q + 1] = p; }

            const float s16  = pre[16];
            const float c10a = pre[10];
            const float c10b = pre[14] - pre[4];
            const float c8a  = pre[8];
            const float c8b  = pre[11] - pre[3];
            const float c8c  = pre[14] - pre[6];

            acc[0] += s16;
            if (h < 10)           { acc[1]  += c10a; acc[2]  += c10b; }
            if (h >= 4 && h < 14) { acc[3]  += c10a; acc[4]  += c10b; }
            if (h < 8)            { acc[5]  += c8a;  acc[6]  += c8b;  acc[7]  += c8c; }
            if (h >= 3 && h < 11) { acc[8]  += c8a;  acc[9]  += c8b;  acc[10] += c8c; }
            if (h >= 6 && h < 14) { acc[11] += c8a;  acc[12] += c8b;  acc[13] += c8c; }
        }
        __syncthreads();     // everyone done reading cur before reusing it

        // ---- combine 8 row-chunk partials per channel via smem (reuse cur) ----
        float* red = cur;                       // 14 * 144 = 2016 floats
        #pragma unroll
        for (int r = 0; r < NREG; r++) red[r * RSTRIDE + t] = acc[r];
        __syncthreads();

        const int b  = tile >> 7;               // 128 tiles per batch
        const int c0 = (tile & 127) * CHB;
        float* __restrict__ outb = out + (size_t)b * OUT_PER_B;
        float ss = 0.0f;
        #pragma unroll
        for (int idx = t; idx < NREG * CHB; idx += TPB) {   // 224 outputs
            const int r  = idx >> 4;
            const int cc = idx & 15;
            float v = 0.0f;
            #pragma unroll
            for (int k = 0; k < 8; k++) v += red[r * RSTRIDE + cc + 16 * k];
            const float inv_area = (r == 0) ? (1.0f / 256.0f)
                                  : (r < 5) ? (1.0f / 100.0f)
                                            : (1.0f / 64.0f);
            v *= inv_area;
            outb[r * C_TOT + c0 + cc] = v;
            ss += v * v;
        }

        // block-reduce ss -> g_part[tile] (plain store, no atomics)
        #pragma unroll
        for (int o = 16; o > 0; o >>= 1)
            ss += __shfl_down_sync(0xffffffffu, ss, o);
        float* wsum = cur + 2048;               // beyond red area, inside buffer
        if ((t & 31) == 0) wsum[t >> 5] = ss;
        __syncthreads();
        if (t == 0) g_part[tile] = wsum[0] + wsum[1] + wsum[2] + wsum[3];
        __syncthreads();     // cur fully consumed -> safe to refill

        const int nt = tile + 2 * GRID_MAIN;
        if (nt < NTILES) issue(nt, j & 1);
        cp_commit();         // commit every iteration to keep group accounting simple
    }
}

// 448 blocks. Latency-overlapped: issue the block's 16 KiB of output loads
// FIRST, then reduce the 128 per-tile partials while those loads are in
// flight, then sync, scale, store.
__global__ __launch_bounds__(256) void rmac_norm_kernel(float* __restrict__ out) {
    const int b = blockIdx.y;
    const int s = blockIdx.x;       // 0..6
    const int t = threadIdx.x;

    float4* __restrict__ p =
        reinterpret_cast<float4*>(out + (size_t)b * OUT_PER_B) + s * 1024 + t;

    // 1) independent output loads go out first (4 x LDG.128 per thread)
    float4 v[4];
    #pragma unroll
    for (int k = 0; k < 4; k++) v[k] = p[k * 256];

    // 2) warp 0 reduces the partials while the loads above are in flight
    __shared__ float sinv;
    if (t < 32) {
        float w = g_part[b * 128 + t]      + g_part[b * 128 + t + 32]
                + g_part[b * 128 + t + 64] + g_part[b * 128 + t + 96];
        #pragma unroll
        for (int o = 16; o > 0; o >>= 1)
            w += __shfl_down_sync(0xffffffffu, w, o);
        if (t == 0) sinv = 1.0f / fmaxf(sqrtf(w), 1e-12f);
    }
    __syncthreads();
    const float inv = sinv;

    // 3) scale + store
    #pragma unroll
    for (int k = 0; k < 4; k++) {
        v[k].x *= inv; v[k].y *= inv; v[k].z *= inv; v[k].w *= inv;
        p[k * 256] = v[k];
    }
}

extern "C" void kernel_launch(void* const* d_in, const int* in_sizes, int n_in,
                              void* d_out, int out_size) {
    (void)in_sizes; (void)n_in; (void)out_size;
    const float* x = (const float*)d_in[0];
    float* out = (float*)d_out;

    rmac_main_kernel<<<GRID_MAIN, TPB>>>(x, out);

    dim3 gn(OUT_PER_B / (256 * 4 * 4), B_TOT);   // (7, 64) = 448 blocks
    rmac_norm_kernel<<<gn, 256>>>(out);
}